// round 5
// baseline (speedup 1.0000x reference)
#include <cuda_runtime.h>

#define FD 128
#define NMAX 100352
#define EMAX 1600000
#define SCAN_CHUNK 4096
#define SCAN_ITEMS 16
#define WS_STRIDE 132
#define GEMM_SMEM ((FD * WS_STRIDE + 8 * 4 * FD) * 4)

// ---------------- scratch (device globals; no allocation) ----------------
__device__ float g_H[(size_t)NMAX * FD];     // GEMM output / SpMM input
__device__ float g_T[(size_t)NMAX * FD];     // layer-1 output
__device__ int   g_col[EMAX];                // CSR column (src) indices
__device__ int   g_cnt[NMAX];                // per-dst edge counts
__device__ int   g_rowptr[NMAX + 1];
__device__ int   g_off[NMAX];                // running offsets for scatter
__device__ float g_dinv[NMAX];               // deg^{-1/2}
__device__ int   g_bsum[256];                // scan block sums

// ---------------- degree / CSR build ----------------
__global__ void k_zero_cnt(int n) {
    int i = blockIdx.x * blockDim.x + threadIdx.x;
    if (i < n) g_cnt[i] = 0;
}

__global__ void k_count(const int* __restrict__ dst, int e) {
    int i = blockIdx.x * blockDim.x + threadIdx.x;
    if (i < e) atomicAdd(&g_cnt[dst[i]], 1);
}

__global__ void k_dinv(int n) {
    int i = blockIdx.x * blockDim.x + threadIdx.x;
    if (i < n) g_dinv[i] = rsqrtf((float)(g_cnt[i] + 1));   // +1 self loop
}

__global__ void k_scanA(int n) {
    __shared__ int s[256];
    int tid = threadIdx.x;
    int base = blockIdx.x * SCAN_CHUNK + tid * SCAN_ITEMS;
    int sum = 0;
#pragma unroll
    for (int t = 0; t < SCAN_ITEMS; t++) {
        int i = base + t;
        if (i < n) sum += g_cnt[i];
    }
    s[tid] = sum;
    __syncthreads();
    for (int d = 128; d > 0; d >>= 1) {
        if (tid < d) s[tid] += s[tid + d];
        __syncthreads();
    }
    if (tid == 0) g_bsum[blockIdx.x] = s[0];
}

__global__ void k_scanB(int nchunks, int n) {
    if (threadIdx.x == 0 && blockIdx.x == 0) {
        int run = 0;
        for (int b = 0; b < nchunks; b++) {
            int t = g_bsum[b];
            g_bsum[b] = run;
            run += t;
        }
        g_rowptr[n] = run;
    }
}

__global__ void k_scanC(int n) {
    __shared__ int s[256];
    int tid = threadIdx.x;
    int base = blockIdx.x * SCAN_CHUNK + tid * SCAN_ITEMS;
    int v[SCAN_ITEMS];
    int local = 0;
#pragma unroll
    for (int t = 0; t < SCAN_ITEMS; t++) {
        int i = base + t;
        v[t] = (i < n) ? g_cnt[i] : 0;
        local += v[t];
    }
    s[tid] = local;
    __syncthreads();
    for (int d = 1; d < 256; d <<= 1) {
        int x = (tid >= d) ? s[tid - d] : 0;
        __syncthreads();
        s[tid] += x;
        __syncthreads();
    }
    int off = g_bsum[blockIdx.x] + s[tid] - local;   // exclusive prefix
#pragma unroll
    for (int t = 0; t < SCAN_ITEMS; t++) {
        int i = base + t;
        if (i < n) {
            g_rowptr[i] = off;
            g_off[i]    = off;
            off += v[t];
        }
    }
}

__global__ void k_scatter(const int* __restrict__ src, const int* __restrict__ dst, int e) {
    int i = blockIdx.x * blockDim.x + threadIdx.x;
    if (i < e) {
        int p = atomicAdd(&g_off[dst[i]], 1);
        g_col[p] = src[i];
    }
}

// ---------------- dense: H = X @ W^T ----------------
// block = 256 threads = 8 warps; each warp computes 4 rows; W^T staged in smem
// (row stride 132 floats: 16B aligned -> conflict-free LDS.128 on the compute path).
__global__ void __launch_bounds__(256) k_gemm(const float* __restrict__ X,
                                              const float* __restrict__ W,
                                              float* __restrict__ Hout, int n) {
    extern __shared__ float smem[];
    float* Ws = smem;                         // [128][132]  Ws[k][c] = W[c][k]
    float* xs = smem + FD * WS_STRIDE;        // [8 warps][4 rows][128]
    int tid = threadIdx.x;
    for (int idx = tid; idx < FD * FD; idx += 256) {
        int c = idx >> 7, k = idx & 127;
        Ws[k * WS_STRIDE + c] = W[idx];
    }
    __syncthreads();

    int warp = tid >> 5, lane = tid & 31;
    int row0 = (blockIdx.x * 8 + warp) * 4;
    float4* xw4 = (float4*)(xs + warp * (4 * FD));
    const float4 z4 = make_float4(0.f, 0.f, 0.f, 0.f);
#pragma unroll
    for (int r = 0; r < 4; r++) {
        int row = row0 + r;
        float4 v = (row < n) ? ((const float4*)X)[(size_t)row * 32 + lane] : z4;
        xw4[r * 32 + lane] = v;
    }
    __syncwarp();

    float4 acc[4] = {z4, z4, z4, z4};
#pragma unroll 4
    for (int g = 0; g < 32; g++) {
        int k = g * 4;
        float4 w0 = ((const float4*)(Ws + (k + 0) * WS_STRIDE))[lane];
        float4 w1 = ((const float4*)(Ws + (k + 1) * WS_STRIDE))[lane];
        float4 w2 = ((const float4*)(Ws + (k + 2) * WS_STRIDE))[lane];
        float4 w3 = ((const float4*)(Ws + (k + 3) * WS_STRIDE))[lane];
#pragma unroll
        for (int r = 0; r < 4; r++) {
            float4 xq = xw4[r * 32 + g];      // broadcast LDS.128
            acc[r].x += xq.x * w0.x + xq.y * w1.x + xq.z * w2.x + xq.w * w3.x;
            acc[r].y += xq.x * w0.y + xq.y * w1.y + xq.z * w2.y + xq.w * w3.y;
            acc[r].z += xq.x * w0.z + xq.y * w1.z + xq.z * w2.z + xq.w * w3.z;
            acc[r].w += xq.x * w0.w + xq.y * w1.w + xq.z * w2.w + xq.w * w3.w;
        }
    }

    float4* H4 = (float4*)Hout;
#pragma unroll
    for (int r = 0; r < 4; r++) {
        int row = row0 + r;
        if (row < n) H4[(size_t)row * 32 + lane] = acc[r];
    }
}

// ---------------- sparse: out[i] = di*sum_j dinv[j]*H[j] + di^2*H[i] + b + pert ----
// one warp per row; lane l owns cols [4l, 4l+4); 4-way unrolled neighbor loop for MLP.
__global__ void __launch_bounds__(256) k_spmm(const float* __restrict__ Hin,
                                              const float* __restrict__ bias,
                                              const float* __restrict__ pert,
                                              float* __restrict__ out, int n) {
    int gw = (blockIdx.x * blockDim.x + threadIdx.x) >> 5;
    int lane = threadIdx.x & 31;
    if (gw >= n) return;
    int i = gw;
    int beg = g_rowptr[i], end = g_rowptr[i + 1];
    const float4* H4 = (const float4*)Hin;
    const float4 z4 = make_float4(0.f, 0.f, 0.f, 0.f);
    float4 a0 = z4, a1 = z4, a2 = z4, a3 = z4;

    int p = beg;
    for (; p + 3 < end; p += 4) {
        int j0 = g_col[p], j1 = g_col[p + 1], j2 = g_col[p + 2], j3 = g_col[p + 3];
        float s0 = g_dinv[j0], s1 = g_dinv[j1], s2 = g_dinv[j2], s3 = g_dinv[j3];
        float4 h0 = H4[(size_t)j0 * 32 + lane];
        float4 h1 = H4[(size_t)j1 * 32 + lane];
        float4 h2 = H4[(size_t)j2 * 32 + lane];
        float4 h3 = H4[(size_t)j3 * 32 + lane];
        a0.x += s0 * h0.x; a0.y += s0 * h0.y; a0.z += s0 * h0.z; a0.w += s0 * h0.w;
        a1.x += s1 * h1.x; a1.y += s1 * h1.y; a1.z += s1 * h1.z; a1.w += s1 * h1.w;
        a2.x += s2 * h2.x; a2.y += s2 * h2.y; a2.z += s2 * h2.z; a2.w += s2 * h2.w;
        a3.x += s3 * h3.x; a3.y += s3 * h3.y; a3.z += s3 * h3.z; a3.w += s3 * h3.w;
    }
    for (; p < end; p++) {
        int j = g_col[p];
        float s = g_dinv[j];
        float4 h = H4[(size_t)j * 32 + lane];
        a0.x += s * h.x; a0.y += s * h.y; a0.z += s * h.z; a0.w += s * h.w;
    }
    float4 acc;
    acc.x = (a0.x + a1.x) + (a2.x + a3.x);
    acc.y = (a0.y + a1.y) + (a2.y + a3.y);
    acc.z = (a0.z + a1.z) + (a2.z + a3.z);
    acc.w = (a0.w + a1.w) + (a2.w + a3.w);

    float di = g_dinv[i];
    float dii = di * di;
    float4 hs = H4[(size_t)i * 32 + lane];
    float4 bv = ((const float4*)bias)[lane];
    float4 pv = ((const float4*)pert)[(size_t)i * 32 + lane];
    float4 res;
    res.x = di * acc.x + dii * hs.x + bv.x + pv.x;
    res.y = di * acc.y + dii * hs.y + bv.y + pv.y;
    res.z = di * acc.z + dii * hs.z + bv.z + pv.z;
    res.w = di * acc.w + dii * hs.w + bv.w + pv.w;
    ((float4*)out)[(size_t)i * 32 + lane] = res;
}

// ---------------- launch ----------------
extern "C" void kernel_launch(void* const* d_in, const int* in_sizes, int n_in,
                              void* d_out, int out_size) {
    const float* x  = (const float*)d_in[0];
    const int*   ei = (const int*)d_in[1];
    const float* pf = (const float*)d_in[2];
    const float* pl = (const float*)d_in[3];
    const float* W1 = (const float*)d_in[4];
    const float* b1 = (const float*)d_in[5];
    const float* W2 = (const float*)d_in[6];
    const float* b2 = (const float*)d_in[7];
    float* out = (float*)d_out;

    int n = in_sizes[0] / FD;
    int e = in_sizes[1] / 2;
    const int* src = ei;
    const int* dst = ei + e;

    void *pH = nullptr, *pT = nullptr;
    cudaGetSymbolAddress(&pH, g_H);
    cudaGetSymbolAddress(&pT, g_T);

    cudaFuncSetAttribute(k_gemm, cudaFuncAttributeMaxDynamicSharedMemorySize, GEMM_SMEM);

    int nb = (n + 255) / 256;
    int eb = (e + 255) / 256;
    int nchunks = (n + SCAN_CHUNK - 1) / SCAN_CHUNK;
    int gb = (n + 31) / 32;   // 32 rows per gemm block
    int sb = (n + 7) / 8;     // 8 warps (rows) per spmm block

    // CSR build + normalization
    k_zero_cnt<<<nb, 256>>>(n);
    k_count<<<eb, 256>>>(dst, e);
    k_dinv<<<nb, 256>>>(n);
    k_scanA<<<nchunks, 256>>>(n);
    k_scanB<<<1, 32>>>(nchunks, n);
    k_scanC<<<nchunks, 256>>>(n);
    k_scatter<<<eb, 256>>>(src, dst, e);

    // layer 1
    k_gemm<<<gb, 256, GEMM_SMEM>>>(x, W1, (float*)pH, n);
    k_spmm<<<sb, 256>>>((const float*)pH, b1, pf, (float*)pT, n);
    // layer 2
    k_gemm<<<gb, 256, GEMM_SMEM>>>((const float*)pT, W2, (float*)pH, n);
    k_spmm<<<sb, 256>>>((const float*)pH, b2, pl, out, n);
}

// round 7
// speedup vs baseline: 1.2720x; 1.2720x over previous
#include <cuda_runtime.h>

#define FD 128
#define NMAX 100352
#define EMAX 1600000
#define SCAN_CHUNK 4096
#define SCAN_ITEMS 16
#define WS_STRIDE 132
#define ROWS_PER_WARP 8
#define GWARPS 8
#define ROWS_PER_BLOCK (ROWS_PER_WARP * GWARPS)
#define GEMM_SMEM ((FD * WS_STRIDE + ROWS_PER_BLOCK * FD) * 4)

// ---------------- scratch (device globals; no allocation) ----------------
__device__ float g_H[(size_t)NMAX * FD];     // GEMM output / SpMM input
__device__ float g_T[(size_t)NMAX * FD];     // layer-1 output
__device__ int   g_col[EMAX];                // CSR column (src) indices
__device__ int   g_cnt[NMAX];                // per-dst edge counts
__device__ int   g_rowptr[NMAX + 1];
__device__ int   g_off[NMAX];                // running offsets for scatter
__device__ float g_dinv[NMAX];               // deg^{-1/2}
__device__ int   g_bsum[256];                // scan block sums

// ---------------- packed fp32x2 helpers (FFMA2 path, PTX-only) ----------------
__device__ __forceinline__ unsigned long long ffma2(unsigned long long a,
                                                    unsigned long long b,
                                                    unsigned long long c) {
    unsigned long long d;
    asm("fma.rn.f32x2 %0, %1, %2, %3;" : "=l"(d) : "l"(a), "l"(b), "l"(c));
    return d;
}
__device__ __forceinline__ unsigned long long pack2(float x) {
    unsigned long long d;
    unsigned int u = __float_as_uint(x);
    asm("mov.b64 %0, {%1, %1};" : "=l"(d) : "r"(u));
    return d;
}

// ---------------- degree / CSR build ----------------
__global__ void k_zero_cnt(int n) {
    int i = blockIdx.x * blockDim.x + threadIdx.x;
    if (i < n) g_cnt[i] = 0;
}

__global__ void k_count(const int* __restrict__ dst, int e) {
    int i = blockIdx.x * blockDim.x + threadIdx.x;
    if (i < e) atomicAdd(&g_cnt[dst[i]], 1);
}

__global__ void k_scanA(int n) {
    __shared__ int s[256];
    int tid = threadIdx.x;
    int base = blockIdx.x * SCAN_CHUNK + tid * SCAN_ITEMS;
    int sum = 0;
#pragma unroll
    for (int t = 0; t < SCAN_ITEMS; t++) {
        int i = base + t;
        if (i < n) sum += g_cnt[i];
    }
    s[tid] = sum;
    __syncthreads();
    for (int d = 128; d > 0; d >>= 1) {
        if (tid < d) s[tid] += s[tid + d];
        __syncthreads();
    }
    if (tid == 0) g_bsum[blockIdx.x] = s[0];
}

__global__ void k_scanB(int nchunks, int n) {
    if (threadIdx.x == 0 && blockIdx.x == 0) {
        int run = 0;
        for (int b = 0; b < nchunks; b++) {
            int t = g_bsum[b];
            g_bsum[b] = run;
            run += t;
        }
        g_rowptr[n] = run;
    }
}

// rowptr/off exclusive scan + dinv (folded here; cnt already in registers)
__global__ void k_scanC(int n) {
    __shared__ int s[256];
    int tid = threadIdx.x;
    int base = blockIdx.x * SCAN_CHUNK + tid * SCAN_ITEMS;
    int v[SCAN_ITEMS];
    int local = 0;
#pragma unroll
    for (int t = 0; t < SCAN_ITEMS; t++) {
        int i = base + t;
        v[t] = (i < n) ? g_cnt[i] : 0;
        local += v[t];
    }
    s[tid] = local;
    __syncthreads();
    for (int d = 1; d < 256; d <<= 1) {
        int x = (tid >= d) ? s[tid - d] : 0;
        __syncthreads();
        s[tid] += x;
        __syncthreads();
    }
    int off = g_bsum[blockIdx.x] + s[tid] - local;   // exclusive prefix
#pragma unroll
    for (int t = 0; t < SCAN_ITEMS; t++) {
        int i = base + t;
        if (i < n) {
            g_rowptr[i] = off;
            g_off[i]    = off;
            g_dinv[i]   = rsqrtf((float)(v[t] + 1));   // +1 self loop
            off += v[t];
        }
    }
}

__global__ void k_scatter(const int* __restrict__ src, const int* __restrict__ dst, int e) {
    int i = blockIdx.x * blockDim.x + threadIdx.x;
    if (i < e) {
        int p = atomicAdd(&g_off[dst[i]], 1);
        g_col[p] = src[i];
    }
}

// ---------------- dense: H = X @ W^T (FFMA2, 8 rows/warp) ----------------
// Ws[k][c] = W[c][k], stride 132 floats (16B-aligned rows -> conflict-free LDS.128).
// Lane l owns cols 4l..4l+3 as two packed f32 pairs; W pairs load directly as
// ulonglong2 from smem; x broadcast (N=1) duplicated into pairs via mov.b64.
__global__ void __launch_bounds__(256) k_gemm(const float* __restrict__ X,
                                              const float* __restrict__ W,
                                              float* __restrict__ Hout, int n) {
    extern __shared__ float smem[];
    float* Ws = smem;                           // [128][132]
    float* xs = smem + FD * WS_STRIDE;          // [8 warps][8 rows][128]
    int tid = threadIdx.x;
    for (int idx = tid; idx < FD * FD; idx += 256) {
        int c = idx >> 7, k = idx & 127;
        Ws[k * WS_STRIDE + c] = W[idx];
    }

    int warp = tid >> 5, lane = tid & 31;
    int row0 = blockIdx.x * ROWS_PER_BLOCK + warp * ROWS_PER_WARP;
    float4* xw4 = (float4*)(xs + warp * ROWS_PER_WARP * FD);
    const float4 z4 = make_float4(0.f, 0.f, 0.f, 0.f);
#pragma unroll
    for (int r = 0; r < ROWS_PER_WARP; r++) {
        int row = row0 + r;
        xw4[r * 32 + lane] = (row < n) ? ((const float4*)X)[(size_t)row * 32 + lane] : z4;
    }
    __syncthreads();

    unsigned long long a01[ROWS_PER_WARP], a23[ROWS_PER_WARP];
#pragma unroll
    for (int r = 0; r < ROWS_PER_WARP; r++) { a01[r] = 0ull; a23[r] = 0ull; }

#pragma unroll 2
    for (int g = 0; g < 32; g++) {
        int k = g * 4;
        ulonglong2 w0 = ((const ulonglong2*)(Ws + (k + 0) * WS_STRIDE))[lane];
        ulonglong2 w1 = ((const ulonglong2*)(Ws + (k + 1) * WS_STRIDE))[lane];
        ulonglong2 w2 = ((const ulonglong2*)(Ws + (k + 2) * WS_STRIDE))[lane];
        ulonglong2 w3 = ((const ulonglong2*)(Ws + (k + 3) * WS_STRIDE))[lane];
#pragma unroll
        for (int r = 0; r < ROWS_PER_WARP; r++) {
            float4 xq = xw4[r * 32 + g];        // broadcast LDS.128 (N=1)
            unsigned long long x0 = pack2(xq.x);
            unsigned long long x1 = pack2(xq.y);
            unsigned long long x2 = pack2(xq.z);
            unsigned long long x3 = pack2(xq.w);
            a01[r] = ffma2(x0, w0.x, a01[r]);
            a01[r] = ffma2(x1, w1.x, a01[r]);
            a01[r] = ffma2(x2, w2.x, a01[r]);
            a01[r] = ffma2(x3, w3.x, a01[r]);
            a23[r] = ffma2(x0, w0.y, a23[r]);
            a23[r] = ffma2(x1, w1.y, a23[r]);
            a23[r] = ffma2(x2, w2.y, a23[r]);
            a23[r] = ffma2(x3, w3.y, a23[r]);
        }
    }

#pragma unroll
    for (int r = 0; r < ROWS_PER_WARP; r++) {
        int row = row0 + r;
        if (row < n) {
            ulonglong2 v;
            v.x = a01[r];
            v.y = a23[r];
            ((ulonglong2*)Hout)[(size_t)row * 32 + lane] = v;
        }
    }
}

// ---------------- sparse: out[i] = di*sum_j dinv[j]*H[j] + di^2*H[i] + b + pert ----
__global__ void __launch_bounds__(256) k_spmm(const float* __restrict__ Hin,
                                              const float* __restrict__ bias,
                                              const float* __restrict__ pert,
                                              float* __restrict__ out, int n) {
    int gw = (blockIdx.x * blockDim.x + threadIdx.x) >> 5;
    int lane = threadIdx.x & 31;
    if (gw >= n) return;
    int i = gw;
    int beg = g_rowptr[i], end = g_rowptr[i + 1];
    const float4* H4 = (const float4*)Hin;
    const float4 z4 = make_float4(0.f, 0.f, 0.f, 0.f);
    float4 a0 = z4, a1 = z4, a2 = z4, a3 = z4;

    int p = beg;
    for (; p + 3 < end; p += 4) {
        int j0 = g_col[p], j1 = g_col[p + 1], j2 = g_col[p + 2], j3 = g_col[p + 3];
        float s0 = g_dinv[j0], s1 = g_dinv[j1], s2 = g_dinv[j2], s3 = g_dinv[j3];
        float4 h0 = H4[(size_t)j0 * 32 + lane];
        float4 h1 = H4[(size_t)j1 * 32 + lane];
        float4 h2 = H4[(size_t)j2 * 32 + lane];
        float4 h3 = H4[(size_t)j3 * 32 + lane];
        a0.x += s0 * h0.x; a0.y += s0 * h0.y; a0.z += s0 * h0.z; a0.w += s0 * h0.w;
        a1.x += s1 * h1.x; a1.y += s1 * h1.y; a1.z += s1 * h1.z; a1.w += s1 * h1.w;
        a2.x += s2 * h2.x; a2.y += s2 * h2.y; a2.z += s2 * h2.z; a2.w += s2 * h2.w;
        a3.x += s3 * h3.x; a3.y += s3 * h3.y; a3.z += s3 * h3.z; a3.w += s3 * h3.w;
    }
    for (; p < end; p++) {
        int j = g_col[p];
        float s = g_dinv[j];
        float4 h = H4[(size_t)j * 32 + lane];
        a0.x += s * h.x; a0.y += s * h.y; a0.z += s * h.z; a0.w += s * h.w;
    }
    float4 acc;
    acc.x = (a0.x + a1.x) + (a2.x + a3.x);
    acc.y = (a0.y + a1.y) + (a2.y + a3.y);
    acc.z = (a0.z + a1.z) + (a2.z + a3.z);
    acc.w = (a0.w + a1.w) + (a2.w + a3.w);

    float di = g_dinv[i];
    float dii = di * di;
    float4 hs = H4[(size_t)i * 32 + lane];
    float4 bv = ((const float4*)bias)[lane];
    float4 pv = ((const float4*)pert)[(size_t)i * 32 + lane];
    float4 res;
    res.x = di * acc.x + dii * hs.x + bv.x + pv.x;
    res.y = di * acc.y + dii * hs.y + bv.y + pv.y;
    res.z = di * acc.z + dii * hs.z + bv.z + pv.z;
    res.w = di * acc.w + dii * hs.w + bv.w + pv.w;
    ((float4*)out)[(size_t)i * 32 + lane] = res;
}

// ---------------- launch ----------------
extern "C" void kernel_launch(void* const* d_in, const int* in_sizes, int n_in,
                              void* d_out, int out_size) {
    const float* x  = (const float*)d_in[0];
    const int*   ei = (const int*)d_in[1];
    const float* pf = (const float*)d_in[2];
    const float* pl = (const float*)d_in[3];
    const float* W1 = (const float*)d_in[4];
    const float* b1 = (const float*)d_in[5];
    const float* W2 = (const float*)d_in[6];
    const float* b2 = (const float*)d_in[7];
    float* out = (float*)d_out;

    int n = in_sizes[0] / FD;
    int e = in_sizes[1] / 2;
    const int* src = ei;
    const int* dst = ei + e;

    void *pH = nullptr, *pT = nullptr;
    cudaGetSymbolAddress(&pH, g_H);
    cudaGetSymbolAddress(&pT, g_T);

    cudaFuncSetAttribute(k_gemm, cudaFuncAttributeMaxDynamicSharedMemorySize, GEMM_SMEM);

    int nb = (n + 255) / 256;
    int eb = (e + 255) / 256;
    int nchunks = (n + SCAN_CHUNK - 1) / SCAN_CHUNK;
    int gb = (n + ROWS_PER_BLOCK - 1) / ROWS_PER_BLOCK;
    int sb = (n + 7) / 8;     // 8 warps (rows) per spmm block

    // Fork CSR build onto a side stream so it overlaps GEMM1.
    // kernel_launch runs only twice (correctness + capture); stream/event
    // creation allocates no device memory and is intentionally not destroyed
    // (destroying a stream mid-capture is illegal).
    cudaStream_t s2 = 0;
    cudaEvent_t ev0 = 0, ev1 = 0;
    bool forked =
        (cudaStreamCreateWithFlags(&s2, cudaStreamNonBlocking) == cudaSuccess) &&
        (cudaEventCreateWithFlags(&ev0, cudaEventDisableTiming) == cudaSuccess) &&
        (cudaEventCreateWithFlags(&ev1, cudaEventDisableTiming) == cudaSuccess);
    cudaStream_t cs = forked ? s2 : (cudaStream_t)0;

    if (forked) {
        cudaEventRecord(ev0, (cudaStream_t)0);
        cudaStreamWaitEvent(s2, ev0, 0);
    }

    // CSR build + normalization (side stream when forked)
    k_zero_cnt<<<nb, 256, 0, cs>>>(n);
    k_count<<<eb, 256, 0, cs>>>(dst, e);
    k_scanA<<<nchunks, 256, 0, cs>>>(n);
    k_scanB<<<1, 32, 0, cs>>>(nchunks, n);
    k_scanC<<<nchunks, 256, 0, cs>>>(n);          // also computes dinv
    k_scatter<<<eb, 256, 0, cs>>>(src, dst, e);
    if (forked) cudaEventRecord(ev1, s2);

    // layer 1 linear overlaps the CSR build
    k_gemm<<<gb, 256, GEMM_SMEM>>>(x, W1, (float*)pH, n);
    if (forked) cudaStreamWaitEvent((cudaStream_t)0, ev1, 0);   // join

    k_spmm<<<sb, 256>>>((const float*)pH, b1, pf, (float*)pT, n);
    // layer 2
    k_gemm<<<gb, 256, GEMM_SMEM>>>((const float*)pT, W2, (float*)pH, n);
    k_spmm<<<sb, 256>>>((const float*)pH, b2, pl, out, n);
}